// round 13
// baseline (speedup 1.0000x reference)
#include <cuda_runtime.h>
#include <cuda_fp16.h>
#include <math.h>
#include <stdint.h>

// Problem constants
#define BSZ  16384
#define HD   256
#define GXD  70
#define GYD  70
#define SWIN 2
#define NKW  25   // 5x5 window

// ---------------- scratch (static device memory, no allocations) ----------------
// fp16 2-term split: A-side layout [hi | lo] (K_ext=2K), W-side [hi | hi]
// C = (A_hi + A_lo) . W_hi = A . W_hi  (dropped term A.W_lo ~ 2^-11 rel)
__device__ __align__(16) __half g_Aext[(size_t)BSZ * 512];
__device__ __align__(16) __half g_Hext[(size_t)BSZ * 512];
__device__ __align__(16) __half g_Wih [(size_t)1024 * 512];
__device__ __align__(16) __half g_Whh [(size_t)1024 * 512];
__device__ __align__(16) __half g_Wout[(size_t)256 * 1024];
__device__ __align__(16) __half g_Cext[(size_t)BSZ * 1024];  // [mixHi|qHi|mixLo|qLo]
__device__ float g_gi[(size_t)BSZ * 1024];
__device__ float g_gh[(size_t)BSZ * 1024];
__device__ float g_sg[(size_t)BSZ * 256];
__device__ float g_ug[(size_t)BSZ * 256];

__device__ __forceinline__ float sigmoidf_(float x) {
    return 1.0f / (1.0f + expf(-x));
}

__device__ __forceinline__ uint32_t smem_u32(const void* p) {
    uint32_t a;
    asm("{ .reg .u64 t; cvta.to.shared.u64 t, %1; cvt.u32.u64 %0, t; }" : "=r"(a) : "l"(p));
    return a;
}

__device__ __forceinline__ void ldsm_x4(uint32_t addr, uint32_t& r0, uint32_t& r1,
                                        uint32_t& r2, uint32_t& r3) {
    asm volatile("ldmatrix.sync.aligned.m8n8.x4.shared.b16 {%0,%1,%2,%3}, [%4];"
                 : "=r"(r0), "=r"(r1), "=r"(r2), "=r"(r3) : "r"(addr));
}

__device__ __forceinline__ void mma16816(float& d0, float& d1, float& d2, float& d3,
                                         uint32_t a0, uint32_t a1, uint32_t a2, uint32_t a3,
                                         uint32_t b0, uint32_t b1) {
    asm volatile("mma.sync.aligned.m16n8k16.row.col.f32.f16.f16.f32 "
                 "{%0,%1,%2,%3}, {%4,%5,%6,%7}, {%8,%9}, {%0,%1,%2,%3};"
                 : "+f"(d0), "+f"(d1), "+f"(d2), "+f"(d3)
                 : "r"(a0), "r"(a1), "r"(a2), "r"(a3), "r"(b0), "r"(b1));
}

#define CP_ASYNC16(dst, src) \
    asm volatile("cp.async.cg.shared.global [%0], [%1], 16;" :: "r"(dst), "l"(src))
#define CP_COMMIT() asm volatile("cp.async.commit_group;")
#define CP_WAIT2()  asm volatile("cp.async.wait_group 2;")

// Swizzled tile: 128 rows x 128B (64 halves), unit' = unit ^ (row&7). 16KB/tile.
#define TILEB   16384
#define STAGEB  32768   // A tile + B tile
#define NSTAGE  3
#define SMEM_BYTES (NSTAGE * STAGEB)

// ---------------- conversion kernels (fp32 -> 2-term fp16 split) ---------------
// A-side layout per row: [hi(K) | lo(K)]
__global__ __launch_bounds__(256) void conv_ah_kernel(const float* __restrict__ input_tensor,
                                                      const float* __restrict__ hidden) {
    size_t i = (size_t)blockIdx.x * 256 + threadIdx.x;   // BSZ*128 threads, 2 cols each
    size_t b = i >> 7;
    int c = (int)(i & 127) * 2;
    const float* src; __half* dst; int stride;
    if (blockIdx.z == 0) { src = input_tensor; dst = g_Aext; stride = 258; }
    else                 { src = hidden;       dst = g_Hext; stride = 256; }
    float2 v = *(const float2*)(src + b * stride + c);
    __half h0 = __float2half(v.x);
    __half h1 = __float2half(v.y);
    __half l0 = __float2half(v.x - __half2float(h0));
    __half l1 = __float2half(v.y - __half2float(h1));
    __half2 hh; hh.x = h0; hh.y = h1;
    __half2 ll; ll.x = l0; ll.y = l1;
    __half* d = dst + b * 512 + c;
    *(__half2*)(d)       = hh;
    *(__half2*)(d + 256) = ll;
}

// W-side layout per row: [hi(K) | hi(K)]; z selects {w_ih, w_hh, w_out}
__global__ __launch_bounds__(256) void conv_w_kernel(const float* __restrict__ w_ih,
                                                     const float* __restrict__ w_hh,
                                                     const float* __restrict__ w_out) {
    const int sel = blockIdx.z;
    const float* src = (sel == 0) ? w_ih : (sel == 1) ? w_hh : w_out;
    __half* dst = (sel == 0) ? g_Wih : (sel == 1) ? g_Whh : g_Wout;
    const int K = (sel == 2) ? 512 : 256;
    const int nblk = (sel == 2) ? 256 : 512;
    if (blockIdx.x >= nblk) return;
    size_t e = ((size_t)blockIdx.x * 256 + threadIdx.x) * 2;
    size_t r = e / (size_t)K;
    int k = (int)(e % (size_t)K);
    float2 v = *(const float2*)(src + r * K + k);
    __half2 hh;
    hh.x = __float2half(v.x);
    hh.y = __float2half(v.y);
    __half* d = dst + r * (size_t)(2 * K) + k;
    *(__half2*)(d)     = hh;
    *(__half2*)(d + K) = hh;
}

// ---------------- pipelined mma.sync GEMM mainloop (proven scheme) --------------
// acc[mt][nt][4]: warp tile 32(m) x 64(n); 8 warps in 4(m) x 2(n).
template <int KEXT>
__device__ __forceinline__ void mma_gemm_main(const __half* __restrict__ A,
                                              const __half* __restrict__ W,
                                              char* smem, float (&acc)[2][8][4]) {
    const int tid = threadIdx.x;
    const int wid = tid >> 5, lane = tid & 31;
    const int wm = (wid & 3) * 32;
    const int wn = (wid >> 2) * 64;
    const uint32_t sbase = smem_u32(smem);

    const int crow0 = tid >> 3, cunit = tid & 7;
    const __half* ga = A + (size_t)(blockIdx.y * 128) * KEXT + cunit * 8;
    const __half* gw = W + (size_t)(blockIdx.x * 128) * KEXT + cunit * 8;

    int rowA[2], rowB[4];
#pragma unroll
    for (int mt = 0; mt < 2; mt++)
        rowA[mt] = wm + mt * 16 + (lane & 8) + (lane & 7);
#pragma unroll
    for (int nt2 = 0; nt2 < 4; nt2++)
        rowB[nt2] = wn + nt2 * 16 + ((lane >> 4) & 1) * 8 + (lane & 7);
    const int uA = lane >> 4;          // 0..1
    const int uB = (lane >> 3) & 1;    // 0..1

    constexpr int NC = KEXT / 64;

    auto issue = [&](int ch) {
        const int s = ch % NSTAGE;
        const uint32_t dA = sbase + s * STAGEB;
        const uint32_t dB = dA + TILEB;
#pragma unroll
        for (int j = 0; j < 4; j++) {
            const int row = crow0 + j * 32;
            const uint32_t off = (uint32_t)row * 128 + (uint32_t)((cunit ^ (row & 7)) * 16);
            const size_t gofs = (size_t)row * KEXT + ch * 64;
            CP_ASYNC16(dA + off, ga + gofs);
            CP_ASYNC16(dB + off, gw + gofs);
        }
        CP_COMMIT();
    };

    issue(0);
    issue(1);
#pragma unroll 1
    for (int ch = 0; ch < NC; ch++) {
        if (ch + 2 < NC) issue(ch + 2); else CP_COMMIT();
        CP_WAIT2();
        __syncthreads();
        const int s = ch % NSTAGE;
        const uint32_t aB = sbase + s * STAGEB;
        const uint32_t bB = aB + TILEB;
#pragma unroll
        for (int ks = 0; ks < 4; ks++) {
            uint32_t a[2][4], b[4][4];
#pragma unroll
            for (int mt = 0; mt < 2; mt++) {
                const int u = ks * 2 + uA;
                const uint32_t addr = aB + (uint32_t)rowA[mt] * 128
                                    + (uint32_t)((u ^ (rowA[mt] & 7)) * 16);
                ldsm_x4(addr, a[mt][0], a[mt][1], a[mt][2], a[mt][3]);
            }
#pragma unroll
            for (int nt2 = 0; nt2 < 4; nt2++) {
                const int u = ks * 2 + uB;
                const uint32_t addr = bB + (uint32_t)rowB[nt2] * 128
                                    + (uint32_t)((u ^ (rowB[nt2] & 7)) * 16);
                ldsm_x4(addr, b[nt2][0], b[nt2][1], b[nt2][2], b[nt2][3]);
            }
#pragma unroll
            for (int mt = 0; mt < 2; mt++)
#pragma unroll
                for (int nt = 0; nt < 8; nt++) {
                    const uint32_t b0 = b[nt >> 1][(nt & 1) * 2 + 0];
                    const uint32_t b1 = b[nt >> 1][(nt & 1) * 2 + 1];
                    mma16816(acc[mt][nt][0], acc[mt][nt][1], acc[mt][nt][2], acc[mt][nt][3],
                             a[mt][0], a[mt][1], a[mt][2], a[mt][3], b0, b1);
                }
        }
        __syncthreads();
    }
}

// ---------------- kernel: gi / gh GEMMs (z=0: feature, z=1: hidden) -------------
__global__ __launch_bounds__(256) void tgemm1_kernel(const float* __restrict__ b_ih,
                                                     const float* __restrict__ b_hh) {
    extern __shared__ char smem[];
    const __half* A = blockIdx.z ? g_Hext : g_Aext;
    const __half* W = blockIdx.z ? g_Whh  : g_Wih;
    const float* bias = blockIdx.z ? b_hh : b_ih;
    float* C          = blockIdx.z ? g_gh : g_gi;

    float acc[2][8][4];
#pragma unroll
    for (int mt = 0; mt < 2; mt++)
#pragma unroll
        for (int nt = 0; nt < 8; nt++)
#pragma unroll
            for (int e = 0; e < 4; e++) acc[mt][nt][e] = 0.0f;

    mma_gemm_main<512>(A, W, smem, acc);

    const int wid = threadIdx.x >> 5, lane = threadIdx.x & 31;
    const int wm = (wid & 3) * 32, wn = (wid >> 2) * 64;
    const int gid = lane >> 2, tig = lane & 3;
#pragma unroll
    for (int mt = 0; mt < 2; mt++) {
        const int r = blockIdx.y * 128 + wm + mt * 16 + gid;
#pragma unroll
        for (int nt = 0; nt < 8; nt++) {
            const int c = blockIdx.x * 128 + wn + nt * 8 + 2 * tig;
            float2 bv = *(const float2*)(bias + c);
            float2 v0 = { acc[mt][nt][0] + bv.x, acc[mt][nt][1] + bv.y };
            float2 v1 = { acc[mt][nt][2] + bv.x, acc[mt][nt][3] + bv.y };
            *(float2*)(C + (size_t)r * 1024 + c)       = v0;
            *(float2*)(C + (size_t)(r + 8) * 1024 + c) = v1;
        }
    }
}

// ---------------- kernel: gates + attention over 5x5 context -------------------
// Two-pass gather with precomputed row-pointer table (kills per-iter index ALU).
__global__ __launch_bounds__(256) void phaseB_kernel(
    const float* __restrict__ input_tensor,
    const float* __restrict__ memory) {
    const int b = blockIdx.x;
    const int t = threadIdx.x;

    __shared__ __align__(16) float q_s[HD];
    __shared__ __align__(16) float attn_p[NKW][2];
    __shared__ __align__(16) float w_s[NKW];
    __shared__ __align__(16) float mixp[4][HD];          // per-k-group mix partials
    __shared__ __align__(16) const float* rowp[NKW + 7]; // gather row pointers

    const float* gi = g_gi + (size_t)b * 1024;
    const float* gh = g_gh + (size_t)b * 1024;
    float i_r = gi[t],       h_r = gh[t];
    float i_i = gi[256 + t], h_i = gh[256 + t];
    float i_n = gi[512 + t], h_n = gh[512 + t];
    float i_s = gi[768 + t], h_s = gh[768 + t];

    float rg = sigmoidf_(i_r + h_r);
    float ug = sigmoidf_(i_i + h_i);
    float sg = sigmoidf_(i_s + h_s);
    float q  = tanhf(i_n + rg * h_n);
    q_s[t] = q;
    g_sg[(size_t)b * HD + t] = sg;
    g_ug[(size_t)b * HD + t] = ug;

    // 25 threads build the clamped gather row-pointer table once
    if (t < NKW) {
        int gx = (int)input_tensor[(size_t)b * 258 + 256] + SWIN;
        int gy = (int)input_tensor[(size_t)b * 258 + 257] + SWIN;
        gx = min(max(gx, 0), GXD - 1);
        gy = min(max(gy, 0), GYD - 1);
        int xi = min(max(gx + t / 5 - SWIN, 0), GXD - 1);
        int yi = min(max(gy + t % 5 - SWIN, 0), GYD - 1);
        rowp[t] = memory + ((size_t)xi * GYD + yi) * HD;
    }

    __syncthreads();   // q_s + rowp ready

    // pass 1: fused gather + partial attention dot (float4); 64 threads per k-row
    const int kq  = t >> 6;          // 0..3 k-group (uniform per warp)
    const int cq  = (t & 63) * 4;    // float4 column base
    const int lane = t & 31;
    const int sub  = (t >> 5) & 1;
    float4 q4 = *(const float4*)(q_s + cq);
#pragma unroll
    for (int base = 0; base < 28; base += 4) {
        const int k = base + kq;
        if (k < NKW) {               // uniform per warp
            float4 v = *(const float4*)(rowp[k] + cq);
            float part = v.x * q4.x + v.y * q4.y + v.z * q4.z + v.w * q4.w;
#pragma unroll
            for (int off = 16; off; off >>= 1)
                part += __shfl_xor_sync(0xffffffffu, part, off);
            if (lane == 0) attn_p[k][sub] = part;
        }
    }
    __syncthreads();

    // softmax over 25 (one warp), attn==0 -> -inf, NaN -> 0 semantics
    if (t < 32) {
        float v = (lane < NKW) ? (attn_p[lane][0] + attn_p[lane][1]) : -INFINITY;
        if (v == 0.0f) v = -INFINITY;
        float mx = v;
#pragma unroll
        for (int off = 16; off; off >>= 1)
            mx = fmaxf(mx, __shfl_xor_sync(0xffffffffu, mx, off));
        float e = (mx == -INFINITY) ? 0.0f : expf(v - mx);
        float den = e;
#pragma unroll
        for (int off = 16; off; off >>= 1)
            den += __shfl_xor_sync(0xffffffffu, den, off);
        float wv = (den > 0.0f) ? (e / den) : 0.0f;
        if (lane < NKW) w_s[lane] = wv;
    }

    // q-dependent Cext writes (independent of mix)
    __half* crow = g_Cext + (size_t)b * 1024;
    {
        __half qh = __float2half(q);
        __half ql = __float2half(q - __half2float(qh));
        crow[256 + t] = qh;   // qHi
        crow[768 + t] = ql;   // qLo
    }
    __syncthreads();

    // pass 2: re-gather (L2/L1 hits) + weighted mix partials per k-group
    {
        float4 m4 = make_float4(0.0f, 0.0f, 0.0f, 0.0f);
#pragma unroll
        for (int base = 0; base < 28; base += 4) {
            const int k = base + kq;
            if (k < NKW) {
                float4 v = *(const float4*)(rowp[k] + cq);
                const float w = w_s[k];
                m4.x = fmaf(w, v.x, m4.x);
                m4.y = fmaf(w, v.y, m4.y);
                m4.z = fmaf(w, v.z, m4.z);
                m4.w = fmaf(w, v.w, m4.w);
            }
        }
        *(float4*)(&mixp[kq][cq]) = m4;
    }
    __syncthreads();

    // combine 4 k-group partials (64 threads) and write mix split
    if (t < 64) {
        const int c0 = t * 4;
        float4 a0 = *(const float4*)(&mixp[0][c0]);
        float4 a1 = *(const float4*)(&mixp[1][c0]);
        float4 a2 = *(const float4*)(&mixp[2][c0]);
        float4 a3 = *(const float4*)(&mixp[3][c0]);
        float mv[4] = { a0.x + a1.x + a2.x + a3.x,
                        a0.y + a1.y + a2.y + a3.y,
                        a0.z + a1.z + a2.z + a3.z,
                        a0.w + a1.w + a2.w + a3.w };
        __half mh[4], ml[4];
#pragma unroll
        for (int e = 0; e < 4; e++) {
            mh[e] = __float2half(mv[e]);
            ml[e] = __float2half(mv[e] - __half2float(mh[e]));
        }
        __half2 h01; h01.x = mh[0]; h01.y = mh[1];
        __half2 h23; h23.x = mh[2]; h23.y = mh[3];
        __half2 l01; l01.x = ml[0]; l01.y = ml[1];
        __half2 l23; l23.x = ml[2]; l23.y = ml[3];
        *(__half2*)(crow + c0)           = h01;   // mixHi
        *(__half2*)(crow + c0 + 2)       = h23;
        *(__half2*)(crow + 512 + c0)     = l01;   // mixLo
        *(__half2*)(crow + 512 + c0 + 2) = l23;
    }
}

// ---------------- kernel: output GEMM + fused GRU epilogue ----------------------
__global__ __launch_bounds__(256) void tgemm2_kernel(const float* __restrict__ b_out,
                                                     const float* __restrict__ hidden,
                                                     float* __restrict__ out) {
    extern __shared__ char smem[];

    float acc[2][8][4];
#pragma unroll
    for (int mt = 0; mt < 2; mt++)
#pragma unroll
        for (int nt = 0; nt < 8; nt++)
#pragma unroll
            for (int e = 0; e < 4; e++) acc[mt][nt][e] = 0.0f;

    mma_gemm_main<1024>(g_Cext, g_Wout, smem, acc);

    const int wid = threadIdx.x >> 5, lane = threadIdx.x & 31;
    const int wm = (wid & 3) * 32, wn = (wid >> 2) * 64;
    const int gid = lane >> 2, tig = lane & 3;
#pragma unroll
    for (int mt = 0; mt < 2; mt++) {
        const int rbase = blockIdx.y * 128 + wm + mt * 16 + gid;
#pragma unroll
        for (int nt = 0; nt < 8; nt++) {
            const int c = blockIdx.x * 128 + wn + nt * 8 + 2 * tig;
            float2 bv = *(const float2*)(b_out + c);
#pragma unroll
            for (int half = 0; half < 2; half++) {
                const int r = rbase + half * 8;
                const __half* crow = g_Cext + (size_t)r * 1024;
                __half2 qh2 = *(const __half2*)(crow + 256 + c);
                __half2 ql2 = *(const __half2*)(crow + 768 + c);
                float2 sg2 = *(const float2*)(g_sg + (size_t)r * 256 + c);
                float2 ug2 = *(const float2*)(g_ug + (size_t)r * 256 + c);
                float2 h2  = *(const float2*)(hidden + (size_t)r * 256 + c);
                float q0 = __half2float(qh2.x) + __half2float(ql2.x);
                float q1 = __half2float(qh2.y) + __half2float(ql2.y);
                float v0 = acc[mt][nt][half * 2 + 0] + bv.x;
                float v1 = acc[mt][nt][half * 2 + 1] + bv.y;
                float a0 = tanhf(v0), a1 = tanhf(v1);
                float cu0 = q0 + sg2.x * a0;
                float cu1 = q1 + sg2.y * a1;
                float2 o;
                o.x = cu0 + ug2.x * (h2.x - cu0);
                o.y = cu1 + ug2.y * (h2.y - cu1);
                *(float2*)(out + (size_t)r * 256 + c) = o;
            }
        }
    }
}

// ---------------- launch ---------------------------------------------------------
extern "C" void kernel_launch(void* const* d_in, const int* in_sizes, int n_in,
                              void* d_out, int out_size) {
    const float* input_tensor = (const float*)d_in[0];  // (B, 258)
    const float* hidden       = (const float*)d_in[1];  // (B, 256)
    const float* w_ih         = (const float*)d_in[2];  // (1024, 256)
    const float* b_ih         = (const float*)d_in[3];  // (1024)
    const float* w_hh         = (const float*)d_in[4];  // (1024, 256)
    const float* b_hh         = (const float*)d_in[5];  // (1024)
    const float* w_out        = (const float*)d_in[6];  // (256, 512)
    const float* b_out        = (const float*)d_in[7];  // (256)
    const float* memory       = (const float*)d_in[8];  // (70, 70, 256)
    float* out = (float*)d_out;                         // (B, 256)

    // Host-side, idempotent, not a stream op (capture-safe).
    cudaFuncSetAttribute(tgemm1_kernel, cudaFuncAttributeMaxDynamicSharedMemorySize, SMEM_BYTES);
    cudaFuncSetAttribute(tgemm2_kernel, cudaFuncAttributeMaxDynamicSharedMemorySize, SMEM_BYTES);

    conv_ah_kernel<<<dim3(8192, 1, 2), 256>>>(input_tensor, hidden);
    conv_w_kernel<<<dim3(512, 1, 3), 256>>>(w_ih, w_hh, w_out);
    tgemm1_kernel<<<dim3(8, 128, 2), 256, SMEM_BYTES>>>(b_ih, b_hh);
    phaseB_kernel<<<BSZ, 256>>>(input_tensor, memory);
    tgemm2_kernel<<<dim3(2, 128), 256, SMEM_BYTES>>>(b_out, hidden, out);
}

// round 14
// speedup vs baseline: 1.2832x; 1.2832x over previous
#include <cuda_runtime.h>
#include <cuda_fp16.h>
#include <math.h>
#include <stdint.h>

// Problem constants
#define BSZ  16384
#define HD   256
#define GXD  70
#define GYD  70
#define SWIN 2
#define NKW  25   // 5x5 window

// ---------------- scratch (static device memory, no allocations) ----------------
// Pure fp16 GEMM operands (hi only). Cext keeps hi+lo halves: the GEMM reads only
// columns [0,512) (mixHi|qHi); the epilogue reconstructs q = qHi+qLo exactly.
__device__ __align__(16) __half g_Aext[(size_t)BSZ * 256];
__device__ __align__(16) __half g_Hext[(size_t)BSZ * 256];
__device__ __align__(16) __half g_Wih [(size_t)1024 * 256];
__device__ __align__(16) __half g_Whh [(size_t)1024 * 256];
__device__ __align__(16) __half g_Wout[(size_t)256 * 512];
__device__ __align__(16) __half g_Cext[(size_t)BSZ * 1024];  // [mixHi|qHi|mixLo|qLo]
__device__ float g_gi[(size_t)BSZ * 1024];
__device__ float g_gh[(size_t)BSZ * 1024];
__device__ float g_sg[(size_t)BSZ * 256];
__device__ float g_ug[(size_t)BSZ * 256];

__device__ __forceinline__ float sigmoidf_(float x) {
    return 1.0f / (1.0f + expf(-x));
}

__device__ __forceinline__ uint32_t smem_u32(const void* p) {
    uint32_t a;
    asm("{ .reg .u64 t; cvta.to.shared.u64 t, %1; cvt.u32.u64 %0, t; }" : "=r"(a) : "l"(p));
    return a;
}

__device__ __forceinline__ void ldsm_x4(uint32_t addr, uint32_t& r0, uint32_t& r1,
                                        uint32_t& r2, uint32_t& r3) {
    asm volatile("ldmatrix.sync.aligned.m8n8.x4.shared.b16 {%0,%1,%2,%3}, [%4];"
                 : "=r"(r0), "=r"(r1), "=r"(r2), "=r"(r3) : "r"(addr));
}

__device__ __forceinline__ void mma16816(float& d0, float& d1, float& d2, float& d3,
                                         uint32_t a0, uint32_t a1, uint32_t a2, uint32_t a3,
                                         uint32_t b0, uint32_t b1) {
    asm volatile("mma.sync.aligned.m16n8k16.row.col.f32.f16.f16.f32 "
                 "{%0,%1,%2,%3}, {%4,%5,%6,%7}, {%8,%9}, {%0,%1,%2,%3};"
                 : "+f"(d0), "+f"(d1), "+f"(d2), "+f"(d3)
                 : "r"(a0), "r"(a1), "r"(a2), "r"(a3), "r"(b0), "r"(b1));
}

#define CP_ASYNC16(dst, src) \
    asm volatile("cp.async.cg.shared.global [%0], [%1], 16;" :: "r"(dst), "l"(src))
#define CP_COMMIT() asm volatile("cp.async.commit_group;")
#define CP_WAIT2()  asm volatile("cp.async.wait_group 2;")

// Swizzled tile: 128 rows x 128B (64 halves), unit' = unit ^ (row&7). 16KB/tile.
#define TILEB   16384
#define STAGEB  32768   // A tile + B tile
#define NSTAGE  3
#define SMEM_BYTES (NSTAGE * STAGEB)

// ---------------- conversion kernels (fp32 -> fp16 hi) --------------------------
__global__ __launch_bounds__(256) void conv_ah_kernel(const float* __restrict__ input_tensor,
                                                      const float* __restrict__ hidden) {
    size_t i = (size_t)blockIdx.x * 256 + threadIdx.x;   // BSZ*128 threads, 2 cols each
    size_t b = i >> 7;
    int c = (int)(i & 127) * 2;
    const float* src; __half* dst; int stride;
    if (blockIdx.z == 0) { src = input_tensor; dst = g_Aext; stride = 258; }
    else                 { src = hidden;       dst = g_Hext; stride = 256; }
    float2 v = *(const float2*)(src + b * stride + c);
    __half2 hh;
    hh.x = __float2half(v.x);
    hh.y = __float2half(v.y);
    *(__half2*)(dst + b * 256 + c) = hh;
}

// z selects {w_ih, w_hh, w_out}; destination is hi-only, same K as source
__global__ __launch_bounds__(256) void conv_w_kernel(const float* __restrict__ w_ih,
                                                     const float* __restrict__ w_hh,
                                                     const float* __restrict__ w_out) {
    const int sel = blockIdx.z;
    const float* src = (sel == 0) ? w_ih : (sel == 1) ? w_hh : w_out;
    __half* dst = (sel == 0) ? g_Wih : (sel == 1) ? g_Whh : g_Wout;
    const int nblk = (sel == 2) ? 256 : 512;   // elems/2/256: (256*512), (1024*256)
    if (blockIdx.x >= nblk) return;
    size_t e = ((size_t)blockIdx.x * 256 + threadIdx.x) * 2;
    float2 v = *(const float2*)(src + e);
    __half2 hh;
    hh.x = __float2half(v.x);
    hh.y = __float2half(v.y);
    *(__half2*)(dst + e) = hh;
}

// ---------------- pipelined mma.sync GEMM mainloop (proven scheme) --------------
// acc[mt][nt][4]: warp tile 32(m) x 64(n); 8 warps in 4(m) x 2(n).
// lda/ldw: row strides of A and W (elements); K covered = KEXT (chunked by 64).
template <int KEXT>
__device__ __forceinline__ void mma_gemm_main(const __half* __restrict__ A, int lda,
                                              const __half* __restrict__ W, int ldw,
                                              char* smem, float (&acc)[2][8][4]) {
    const int tid = threadIdx.x;
    const int wid = tid >> 5, lane = tid & 31;
    const int wm = (wid & 3) * 32;
    const int wn = (wid >> 2) * 64;
    const uint32_t sbase = smem_u32(smem);

    const int crow0 = tid >> 3, cunit = tid & 7;
    const __half* ga = A + (size_t)(blockIdx.y * 128) * lda + cunit * 8;
    const __half* gw = W + (size_t)(blockIdx.x * 128) * ldw + cunit * 8;

    int rowA[2], rowB[4];
#pragma unroll
    for (int mt = 0; mt < 2; mt++)
        rowA[mt] = wm + mt * 16 + (lane & 8) + (lane & 7);
#pragma unroll
    for (int nt2 = 0; nt2 < 4; nt2++)
        rowB[nt2] = wn + nt2 * 16 + ((lane >> 4) & 1) * 8 + (lane & 7);
    const int uA = lane >> 4;          // 0..1
    const int uB = (lane >> 3) & 1;    // 0..1

    constexpr int NC = KEXT / 64;

    auto issue = [&](int ch) {
        const int s = ch % NSTAGE;
        const uint32_t dA = sbase + s * STAGEB;
        const uint32_t dB = dA + TILEB;
#pragma unroll
        for (int j = 0; j < 4; j++) {
            const int row = crow0 + j * 32;
            const uint32_t off = (uint32_t)row * 128 + (uint32_t)((cunit ^ (row & 7)) * 16);
            CP_ASYNC16(dA + off, ga + (size_t)row * lda + ch * 64);
            CP_ASYNC16(dB + off, gw + (size_t)row * ldw + ch * 64);
        }
        CP_COMMIT();
    };

    issue(0);
    issue(1);
#pragma unroll 1
    for (int ch = 0; ch < NC; ch++) {
        if (ch + 2 < NC) issue(ch + 2); else CP_COMMIT();
        CP_WAIT2();
        __syncthreads();
        const int s = ch % NSTAGE;
        const uint32_t aB = sbase + s * STAGEB;
        const uint32_t bB = aB + TILEB;
#pragma unroll
        for (int ks = 0; ks < 4; ks++) {
            uint32_t a[2][4], b[4][4];
#pragma unroll
            for (int mt = 0; mt < 2; mt++) {
                const int u = ks * 2 + uA;
                const uint32_t addr = aB + (uint32_t)rowA[mt] * 128
                                    + (uint32_t)((u ^ (rowA[mt] & 7)) * 16);
                ldsm_x4(addr, a[mt][0], a[mt][1], a[mt][2], a[mt][3]);
            }
#pragma unroll
            for (int nt2 = 0; nt2 < 4; nt2++) {
                const int u = ks * 2 + uB;
                const uint32_t addr = bB + (uint32_t)rowB[nt2] * 128
                                    + (uint32_t)((u ^ (rowB[nt2] & 7)) * 16);
                ldsm_x4(addr, b[nt2][0], b[nt2][1], b[nt2][2], b[nt2][3]);
            }
#pragma unroll
            for (int mt = 0; mt < 2; mt++)
#pragma unroll
                for (int nt = 0; nt < 8; nt++) {
                    const uint32_t b0 = b[nt >> 1][(nt & 1) * 2 + 0];
                    const uint32_t b1 = b[nt >> 1][(nt & 1) * 2 + 1];
                    mma16816(acc[mt][nt][0], acc[mt][nt][1], acc[mt][nt][2], acc[mt][nt][3],
                             a[mt][0], a[mt][1], a[mt][2], a[mt][3], b0, b1);
                }
        }
        __syncthreads();
    }
}

// ---------------- kernel: gi / gh GEMMs (z=0: feature, z=1: hidden) -------------
__global__ __launch_bounds__(256) void tgemm1_kernel(const float* __restrict__ b_ih,
                                                     const float* __restrict__ b_hh) {
    extern __shared__ char smem[];
    const __half* A = blockIdx.z ? g_Hext : g_Aext;
    const __half* W = blockIdx.z ? g_Whh  : g_Wih;
    const float* bias = blockIdx.z ? b_hh : b_ih;
    float* C          = blockIdx.z ? g_gh : g_gi;

    float acc[2][8][4];
#pragma unroll
    for (int mt = 0; mt < 2; mt++)
#pragma unroll
        for (int nt = 0; nt < 8; nt++)
#pragma unroll
            for (int e = 0; e < 4; e++) acc[mt][nt][e] = 0.0f;

    mma_gemm_main<256>(A, 256, W, 256, smem, acc);

    const int wid = threadIdx.x >> 5, lane = threadIdx.x & 31;
    const int wm = (wid & 3) * 32, wn = (wid >> 2) * 64;
    const int gid = lane >> 2, tig = lane & 3;
#pragma unroll
    for (int mt = 0; mt < 2; mt++) {
        const int r = blockIdx.y * 128 + wm + mt * 16 + gid;
#pragma unroll
        for (int nt = 0; nt < 8; nt++) {
            const int c = blockIdx.x * 128 + wn + nt * 8 + 2 * tig;
            float2 bv = *(const float2*)(bias + c);
            float2 v0 = { acc[mt][nt][0] + bv.x, acc[mt][nt][1] + bv.y };
            float2 v1 = { acc[mt][nt][2] + bv.x, acc[mt][nt][3] + bv.y };
            *(float2*)(C + (size_t)r * 1024 + c)       = v0;
            *(float2*)(C + (size_t)(r + 8) * 1024 + c) = v1;
        }
    }
}

// ---------------- kernel: gates + attention over 5x5 context (R12-proven) ------
// Two-pass gather (no ctx smem): pass1 fused gather+dot, pass2 re-gather+mix.
__global__ __launch_bounds__(256) void phaseB_kernel(
    const float* __restrict__ input_tensor,
    const float* __restrict__ memory) {
    const int b = blockIdx.x;
    const int t = threadIdx.x;

    __shared__ __align__(16) float q_s[HD];
    __shared__ __align__(16) float attn_p[NKW][2];
    __shared__ __align__(16) float w_s[NKW];
    __shared__ __align__(16) float mixp[4][HD];   // per-k-group mix partials

    const float* gi = g_gi + (size_t)b * 1024;
    const float* gh = g_gh + (size_t)b * 1024;
    float i_r = gi[t],       h_r = gh[t];
    float i_i = gi[256 + t], h_i = gh[256 + t];
    float i_n = gi[512 + t], h_n = gh[512 + t];
    float i_s = gi[768 + t], h_s = gh[768 + t];

    float rg = sigmoidf_(i_r + h_r);
    float ug = sigmoidf_(i_i + h_i);
    float sg = sigmoidf_(i_s + h_s);
    float q  = tanhf(i_n + rg * h_n);
    q_s[t] = q;
    g_sg[(size_t)b * HD + t] = sg;
    g_ug[(size_t)b * HD + t] = ug;

    int gx = (int)input_tensor[(size_t)b * 258 + 256] + SWIN;
    int gy = (int)input_tensor[(size_t)b * 258 + 257] + SWIN;
    gx = min(max(gx, 0), GXD - 1);
    gy = min(max(gy, 0), GYD - 1);

    __syncthreads();   // q_s ready for the fused dot

    // pass 1: fused gather + partial attention dot (float4); 64 threads per k-row
    const int kq  = t >> 6;          // 0..3 k-group
    const int cq  = (t & 63) * 4;    // float4 column base
    const int lane = t & 31;
    const int sub  = (t >> 5) & 1;
    float4 q4 = *(const float4*)(q_s + cq);
#pragma unroll
    for (int base = 0; base < 28; base += 4) {
        const int k = base + kq;
        if (k < NKW) {               // uniform per warp (64-thread groups)
            int xi = min(max(gx + k / 5 - SWIN, 0), GXD - 1);
            int yi = min(max(gy + k % 5 - SWIN, 0), GYD - 1);
            float4 v = *(const float4*)(memory + ((size_t)xi * GYD + yi) * HD + cq);
            float part = v.x * q4.x + v.y * q4.y + v.z * q4.z + v.w * q4.w;
#pragma unroll
            for (int off = 16; off; off >>= 1)
                part += __shfl_xor_sync(0xffffffffu, part, off);
            if (lane == 0) attn_p[k][sub] = part;
        }
    }
    __syncthreads();

    // softmax over 25 (one warp), attn==0 -> -inf, NaN -> 0 semantics
    if (t < 32) {
        float v = (lane < NKW) ? (attn_p[lane][0] + attn_p[lane][1]) : -INFINITY;
        if (v == 0.0f) v = -INFINITY;
        float mx = v;
#pragma unroll
        for (int off = 16; off; off >>= 1)
            mx = fmaxf(mx, __shfl_xor_sync(0xffffffffu, mx, off));
        float e = (mx == -INFINITY) ? 0.0f : expf(v - mx);
        float den = e;
#pragma unroll
        for (int off = 16; off; off >>= 1)
            den += __shfl_xor_sync(0xffffffffu, den, off);
        float wv = (den > 0.0f) ? (e / den) : 0.0f;
        if (lane < NKW) w_s[lane] = wv;
    }

    // q-dependent Cext writes (independent of mix)
    __half* crow = g_Cext + (size_t)b * 1024;
    {
        __half qh = __float2half(q);
        __half ql = __float2half(q - __half2float(qh));
        crow[256 + t] = qh;   // qHi
        crow[768 + t] = ql;   // qLo
    }
    __syncthreads();

    // pass 2: re-gather (L2/L1 hits) + weighted mix partials per k-group
    {
        float4 m4 = make_float4(0.0f, 0.0f, 0.0f, 0.0f);
#pragma unroll
        for (int base = 0; base < 28; base += 4) {
            const int k = base + kq;
            if (k < NKW) {
                int xi = min(max(gx + k / 5 - SWIN, 0), GXD - 1);
                int yi = min(max(gy + k % 5 - SWIN, 0), GYD - 1);
                float4 v = *(const float4*)(memory + ((size_t)xi * GYD + yi) * HD + cq);
                const float w = w_s[k];
                m4.x = fmaf(w, v.x, m4.x);
                m4.y = fmaf(w, v.y, m4.y);
                m4.z = fmaf(w, v.z, m4.z);
                m4.w = fmaf(w, v.w, m4.w);
            }
        }
        *(float4*)(&mixp[kq][cq]) = m4;
    }
    __syncthreads();

    // combine 4 k-group partials (64 threads) and write mix split
    if (t < 64) {
        const int c0 = t * 4;
        float4 a0 = *(const float4*)(&mixp[0][c0]);
        float4 a1 = *(const float4*)(&mixp[1][c0]);
        float4 a2 = *(const float4*)(&mixp[2][c0]);
        float4 a3 = *(const float4*)(&mixp[3][c0]);
        float mv[4] = { a0.x + a1.x + a2.x + a3.x,
                        a0.y + a1.y + a2.y + a3.y,
                        a0.z + a1.z + a2.z + a3.z,
                        a0.w + a1.w + a2.w + a3.w };
        __half mh[4], ml[4];
#pragma unroll
        for (int e = 0; e < 4; e++) {
            mh[e] = __float2half(mv[e]);
            ml[e] = __float2half(mv[e] - __half2float(mh[e]));
        }
        __half2 h01; h01.x = mh[0]; h01.y = mh[1];
        __half2 h23; h23.x = mh[2]; h23.y = mh[3];
        __half2 l01; l01.x = ml[0]; l01.y = ml[1];
        __half2 l23; l23.x = ml[2]; l23.y = ml[3];
        *(__half2*)(crow + c0)           = h01;   // mixHi
        *(__half2*)(crow + c0 + 2)       = h23;
        *(__half2*)(crow + 512 + c0)     = l01;   // mixLo
        *(__half2*)(crow + 512 + c0 + 2) = l23;
    }
}

// ---------------- kernel: output GEMM + fused GRU epilogue ----------------------
__global__ __launch_bounds__(256) void tgemm2_kernel(const float* __restrict__ b_out,
                                                     const float* __restrict__ hidden,
                                                     float* __restrict__ out) {
    extern __shared__ char smem[];

    float acc[2][8][4];
#pragma unroll
    for (int mt = 0; mt < 2; mt++)
#pragma unroll
        for (int nt = 0; nt < 8; nt++)
#pragma unroll
            for (int e = 0; e < 4; e++) acc[mt][nt][e] = 0.0f;

    // GEMM over hi columns only (K=512); Cext row stride = 1024
    mma_gemm_main<512>(g_Cext, 1024, g_Wout, 512, smem, acc);

    const int wid = threadIdx.x >> 5, lane = threadIdx.x & 31;
    const int wm = (wid & 3) * 32, wn = (wid >> 2) * 64;
    const int gid = lane >> 2, tig = lane & 3;
#pragma unroll
    for (int mt = 0; mt < 2; mt++) {
        const int rbase = blockIdx.y * 128 + wm + mt * 16 + gid;
#pragma unroll
        for (int nt = 0; nt < 8; nt++) {
            const int c = blockIdx.x * 128 + wn + nt * 8 + 2 * tig;
            float2 bv = *(const float2*)(b_out + c);
#pragma unroll
            for (int half = 0; half < 2; half++) {
                const int r = rbase + half * 8;
                const __half* crow = g_Cext + (size_t)r * 1024;
                __half2 qh2 = *(const __half2*)(crow + 256 + c);
                __half2 ql2 = *(const __half2*)(crow + 768 + c);
                float2 sg2 = *(const float2*)(g_sg + (size_t)r * 256 + c);
                float2 ug2 = *(const float2*)(g_ug + (size_t)r * 256 + c);
                float2 h2  = *(const float2*)(hidden + (size_t)r * 256 + c);
                float q0 = __half2float(qh2.x) + __half2float(ql2.x);
                float q1 = __half2float(qh2.y) + __half2float(ql2.y);
                float v0 = acc[mt][nt][half * 2 + 0] + bv.x;
                float v1 = acc[mt][nt][half * 2 + 1] + bv.y;
                float a0 = tanhf(v0), a1 = tanhf(v1);
                float cu0 = q0 + sg2.x * a0;
                float cu1 = q1 + sg2.y * a1;
                float2 o;
                o.x = cu0 + ug2.x * (h2.x - cu0);
                o.y = cu1 + ug2.y * (h2.y - cu1);
                *(float2*)(out + (size_t)r * 256 + c) = o;
            }
        }
    }
}

// ---------------- launch ---------------------------------------------------------
extern "C" void kernel_launch(void* const* d_in, const int* in_sizes, int n_in,
                              void* d_out, int out_size) {
    const float* input_tensor = (const float*)d_in[0];  // (B, 258)
    const float* hidden       = (const float*)d_in[1];  // (B, 256)
    const float* w_ih         = (const float*)d_in[2];  // (1024, 256)
    const float* b_ih         = (const float*)d_in[3];  // (1024)
    const float* w_hh         = (const float*)d_in[4];  // (1024, 256)
    const float* b_hh         = (const float*)d_in[5];  // (1024)
    const float* w_out        = (const float*)d_in[6];  // (256, 512)
    const float* b_out        = (const float*)d_in[7];  // (256)
    const float* memory       = (const float*)d_in[8];  // (70, 70, 256)
    float* out = (float*)d_out;                         // (B, 256)

    // Host-side, idempotent, not a stream op (capture-safe).
    cudaFuncSetAttribute(tgemm1_kernel, cudaFuncAttributeMaxDynamicSharedMemorySize, SMEM_BYTES);
    cudaFuncSetAttribute(tgemm2_kernel, cudaFuncAttributeMaxDynamicSharedMemorySize, SMEM_BYTES);

    conv_ah_kernel<<<dim3(8192, 1, 2), 256>>>(input_tensor, hidden);
    conv_w_kernel<<<dim3(512, 1, 3), 256>>>(w_ih, w_hh, w_out);
    tgemm1_kernel<<<dim3(8, 128, 2), 256, SMEM_BYTES>>>(b_ih, b_hh);
    phaseB_kernel<<<BSZ, 256>>>(input_tensor, memory);
    tgemm2_kernel<<<dim3(2, 128), 256, SMEM_BYTES>>>(b_out, hidden, out);
}

// round 15
// speedup vs baseline: 1.2872x; 1.0032x over previous
#include <cuda_runtime.h>
#include <cuda_fp16.h>
#include <math.h>
#include <stdint.h>

// Problem constants
#define BSZ  16384
#define HD   256
#define GXD  70
#define GYD  70
#define SWIN 2
#define NKW  25   // 5x5 window

// ---------------- scratch (static device memory, no allocations) ----------------
// Pure fp16 GEMM operands (hi only). Cext keeps hi+lo halves: the GEMM reads only
// columns [0,512) (mixHi|qHi); the epilogue reconstructs q = qHi+qLo exactly.
__device__ __align__(16) __half g_Aext[(size_t)BSZ * 256];
__device__ __align__(16) __half g_Hext[(size_t)BSZ * 256];
__device__ __align__(16) __half g_Wih [(size_t)1024 * 256];
__device__ __align__(16) __half g_Whh [(size_t)1024 * 256];
__device__ __align__(16) __half g_Wout[(size_t)256 * 512];
__device__ __align__(16) __half g_Cext[(size_t)BSZ * 1024];  // [mixHi|qHi|mixLo|qLo]
__device__ float g_gi[(size_t)BSZ * 1024];
__device__ float g_gh[(size_t)BSZ * 1024];
__device__ float g_sg[(size_t)BSZ * 256];
__device__ float g_ug[(size_t)BSZ * 256];

__device__ __forceinline__ float sigmoidf_(float x) {
    return 1.0f / (1.0f + expf(-x));
}

__device__ __forceinline__ uint32_t smem_u32(const void* p) {
    uint32_t a;
    asm("{ .reg .u64 t; cvta.to.shared.u64 t, %1; cvt.u32.u64 %0, t; }" : "=r"(a) : "l"(p));
    return a;
}

__device__ __forceinline__ void ldsm_x4(uint32_t addr, uint32_t& r0, uint32_t& r1,
                                        uint32_t& r2, uint32_t& r3) {
    asm volatile("ldmatrix.sync.aligned.m8n8.x4.shared.b16 {%0,%1,%2,%3}, [%4];"
                 : "=r"(r0), "=r"(r1), "=r"(r2), "=r"(r3) : "r"(addr));
}

__device__ __forceinline__ void mma16816(float& d0, float& d1, float& d2, float& d3,
                                         uint32_t a0, uint32_t a1, uint32_t a2, uint32_t a3,
                                         uint32_t b0, uint32_t b1) {
    asm volatile("mma.sync.aligned.m16n8k16.row.col.f32.f16.f16.f32 "
                 "{%0,%1,%2,%3}, {%4,%5,%6,%7}, {%8,%9}, {%0,%1,%2,%3};"
                 : "+f"(d0), "+f"(d1), "+f"(d2), "+f"(d3)
                 : "r"(a0), "r"(a1), "r"(a2), "r"(a3), "r"(b0), "r"(b1));
}

#define CP_ASYNC16(dst, src) \
    asm volatile("cp.async.cg.shared.global [%0], [%1], 16;" :: "r"(dst), "l"(src))
#define CP_COMMIT() asm volatile("cp.async.commit_group;")
#define CP_WAIT2()  asm volatile("cp.async.wait_group 2;")

// Swizzled tile: 128 rows x 128B (64 halves), unit' = unit ^ (row&7). 16KB/tile.
#define TILEB   16384
#define STAGEB  32768   // A tile + B tile
#define NSTAGE  3
#define SMEM_BYTES (NSTAGE * STAGEB)

// ---------------- conversion kernels (fp32 -> fp16 hi) --------------------------
__global__ __launch_bounds__(256) void conv_ah_kernel(const float* __restrict__ input_tensor,
                                                      const float* __restrict__ hidden) {
    size_t i = (size_t)blockIdx.x * 256 + threadIdx.x;   // BSZ*128 threads, 2 cols each
    size_t b = i >> 7;
    int c = (int)(i & 127) * 2;
    const float* src; __half* dst; int stride;
    if (blockIdx.z == 0) { src = input_tensor; dst = g_Aext; stride = 258; }
    else                 { src = hidden;       dst = g_Hext; stride = 256; }
    float2 v = *(const float2*)(src + b * stride + c);
    __half2 hh;
    hh.x = __float2half(v.x);
    hh.y = __float2half(v.y);
    *(__half2*)(dst + b * 256 + c) = hh;
}

// z selects {w_ih, w_hh, w_out}; destination is hi-only, same K as source
__global__ __launch_bounds__(256) void conv_w_kernel(const float* __restrict__ w_ih,
                                                     const float* __restrict__ w_hh,
                                                     const float* __restrict__ w_out) {
    const int sel = blockIdx.z;
    const float* src = (sel == 0) ? w_ih : (sel == 1) ? w_hh : w_out;
    __half* dst = (sel == 0) ? g_Wih : (sel == 1) ? g_Whh : g_Wout;
    const int nblk = (sel == 2) ? 256 : 512;
    if (blockIdx.x >= nblk) return;
    size_t e = ((size_t)blockIdx.x * 256 + threadIdx.x) * 2;
    float2 v = *(const float2*)(src + e);
    __half2 hh;
    hh.x = __float2half(v.x);
    hh.y = __float2half(v.y);
    *(__half2*)(dst + e) = hh;
}

// ---------------- pipelined mma.sync GEMM mainloop --------------------------------
// 128 threads, 4 warps in 2(m) x 2(n); warp tile 64x64; CTA tile 128x128.
// acc[mt][nt][4]: mt<4 (16-row tiles), nt<8 (8-col tiles).
// Ratio: 8 ldsm.x4 per 32 MMAs per k16-step (crossbar traffic x0.67 vs 32x64).
template <int KEXT>
__device__ __forceinline__ void mma_gemm_main(const __half* __restrict__ A, int lda,
                                              const __half* __restrict__ W, int ldw,
                                              char* smem, float (&acc)[4][8][4]) {
    const int tid = threadIdx.x;
    const int wid = tid >> 5, lane = tid & 31;
    const int wm = (wid & 1) * 64;
    const int wn = (wid >> 1) * 64;
    const uint32_t sbase = smem_u32(smem);

    // copy mapping: 128 threads; thread handles unit (tid&7), rows (tid>>3)+j*16
    const int crow0 = tid >> 3, cunit = tid & 7;
    const __half* ga = A + (size_t)(blockIdx.y * 128) * lda + cunit * 8;
    const __half* gw = W + (size_t)(blockIdx.x * 128) * ldw + cunit * 8;

    int rowA[4], rowB[4];
#pragma unroll
    for (int mt = 0; mt < 4; mt++)
        rowA[mt] = wm + mt * 16 + (lane & 8) + (lane & 7);
#pragma unroll
    for (int nt2 = 0; nt2 < 4; nt2++)
        rowB[nt2] = wn + nt2 * 16 + ((lane >> 4) & 1) * 8 + (lane & 7);
    const int uA = lane >> 4;          // 0..1
    const int uB = (lane >> 3) & 1;    // 0..1

    constexpr int NC = KEXT / 64;

    auto issue = [&](int ch) {
        const int s = ch % NSTAGE;
        const uint32_t dA = sbase + s * STAGEB;
        const uint32_t dB = dA + TILEB;
#pragma unroll
        for (int j = 0; j < 8; j++) {
            const int row = crow0 + j * 16;
            const uint32_t off = (uint32_t)row * 128 + (uint32_t)((cunit ^ (row & 7)) * 16);
            CP_ASYNC16(dA + off, ga + (size_t)row * lda + ch * 64);
            CP_ASYNC16(dB + off, gw + (size_t)row * ldw + ch * 64);
        }
        CP_COMMIT();
    };

    issue(0);
    issue(1);
#pragma unroll 1
    for (int ch = 0; ch < NC; ch++) {
        if (ch + 2 < NC) issue(ch + 2); else CP_COMMIT();
        CP_WAIT2();
        __syncthreads();
        const int s = ch % NSTAGE;
        const uint32_t aB = sbase + s * STAGEB;
        const uint32_t bB = aB + TILEB;
#pragma unroll
        for (int ks = 0; ks < 4; ks++) {
            uint32_t a[4][4], b[4][4];
#pragma unroll
            for (int mt = 0; mt < 4; mt++) {
                const int u = ks * 2 + uA;
                const uint32_t addr = aB + (uint32_t)rowA[mt] * 128
                                    + (uint32_t)((u ^ (rowA[mt] & 7)) * 16);
                ldsm_x4(addr, a[mt][0], a[mt][1], a[mt][2], a[mt][3]);
            }
#pragma unroll
            for (int nt2 = 0; nt2 < 4; nt2++) {
                const int u = ks * 2 + uB;
                const uint32_t addr = bB + (uint32_t)rowB[nt2] * 128
                                    + (uint32_t)((u ^ (rowB[nt2] & 7)) * 16);
                ldsm_x4(addr, b[nt2][0], b[nt2][1], b[nt2][2], b[nt2][3]);
            }
#pragma unroll
            for (int mt = 0; mt < 4; mt++)
#pragma unroll
                for (int nt = 0; nt < 8; nt++) {
                    const uint32_t b0 = b[nt >> 1][(nt & 1) * 2 + 0];
                    const uint32_t b1 = b[nt >> 1][(nt & 1) * 2 + 1];
                    mma16816(acc[mt][nt][0], acc[mt][nt][1], acc[mt][nt][2], acc[mt][nt][3],
                             a[mt][0], a[mt][1], a[mt][2], a[mt][3], b0, b1);
                }
        }
        __syncthreads();
    }
}

// ---------------- kernel: gi / gh GEMMs (z=0: feature, z=1: hidden) -------------
__global__ __launch_bounds__(128) void tgemm1_kernel(const float* __restrict__ b_ih,
                                                     const float* __restrict__ b_hh) {
    extern __shared__ char smem[];
    const __half* A = blockIdx.z ? g_Hext : g_Aext;
    const __half* W = blockIdx.z ? g_Whh  : g_Wih;
    const float* bias = blockIdx.z ? b_hh : b_ih;
    float* C          = blockIdx.z ? g_gh : g_gi;

    float acc[4][8][4];
#pragma unroll
    for (int mt = 0; mt < 4; mt++)
#pragma unroll
        for (int nt = 0; nt < 8; nt++)
#pragma unroll
            for (int e = 0; e < 4; e++) acc[mt][nt][e] = 0.0f;

    mma_gemm_main<256>(A, 256, W, 256, smem, acc);

    const int wid = threadIdx.x >> 5, lane = threadIdx.x & 31;
    const int wm = (wid & 1) * 64, wn = (wid >> 1) * 64;
    const int gid = lane >> 2, tig = lane & 3;
#pragma unroll
    for (int mt = 0; mt < 4; mt++) {
        const int r = blockIdx.y * 128 + wm + mt * 16 + gid;
#pragma unroll
        for (int nt = 0; nt < 8; nt++) {
            const int c = blockIdx.x * 128 + wn + nt * 8 + 2 * tig;
            float2 bv = *(const float2*)(bias + c);
            float2 v0 = { acc[mt][nt][0] + bv.x, acc[mt][nt][1] + bv.y };
            float2 v1 = { acc[mt][nt][2] + bv.x, acc[mt][nt][3] + bv.y };
            *(float2*)(C + (size_t)r * 1024 + c)       = v0;
            *(float2*)(C + (size_t)(r + 8) * 1024 + c) = v1;
        }
    }
}

// ---------------- kernel: gates + attention over 5x5 context (R12-proven) ------
// Two-pass gather (no ctx smem): pass1 fused gather+dot, pass2 re-gather+mix.
__global__ __launch_bounds__(256) void phaseB_kernel(
    const float* __restrict__ input_tensor,
    const float* __restrict__ memory) {
    const int b = blockIdx.x;
    const int t = threadIdx.x;

    __shared__ __align__(16) float q_s[HD];
    __shared__ __align__(16) float attn_p[NKW][2];
    __shared__ __align__(16) float w_s[NKW];
    __shared__ __align__(16) float mixp[4][HD];   // per-k-group mix partials

    const float* gi = g_gi + (size_t)b * 1024;
    const float* gh = g_gh + (size_t)b * 1024;
    float i_r = gi[t],       h_r = gh[t];
    float i_i = gi[256 + t], h_i = gh[256 + t];
    float i_n = gi[512 + t], h_n = gh[512 + t];
    float i_s = gi[768 + t], h_s = gh[768 + t];

    float rg = sigmoidf_(i_r + h_r);
    float ug = sigmoidf_(i_i + h_i);
    float sg = sigmoidf_(i_s + h_s);
    float q  = tanhf(i_n + rg * h_n);
    q_s[t] = q;
    g_sg[(size_t)b * HD + t] = sg;
    g_ug[(size_t)b * HD + t] = ug;

    int gx = (int)input_tensor[(size_t)b * 258 + 256] + SWIN;
    int gy = (int)input_tensor[(size_t)b * 258 + 257] + SWIN;
    gx = min(max(gx, 0), GXD - 1);
    gy = min(max(gy, 0), GYD - 1);

    __syncthreads();   // q_s ready for the fused dot

    // pass 1: fused gather + partial attention dot (float4); 64 threads per k-row
    const int kq  = t >> 6;          // 0..3 k-group
    const int cq  = (t & 63) * 4;    // float4 column base
    const int lane = t & 31;
    const int sub  = (t >> 5) & 1;
    float4 q4 = *(const float4*)(q_s + cq);
#pragma unroll
    for (int base = 0; base < 28; base += 4) {
        const int k = base + kq;
        if (k < NKW) {               // uniform per warp (64-thread groups)
            int xi = min(max(gx + k / 5 - SWIN, 0), GXD - 1);
            int yi = min(max(gy + k % 5 - SWIN, 0), GYD - 1);
            float4 v = *(const float4*)(memory + ((size_t)xi * GYD + yi) * HD + cq);
            float part = v.x * q4.x + v.y * q4.y + v.z * q4.z + v.w * q4.w;
#pragma unroll
            for (int off = 16; off; off >>= 1)
                part += __shfl_xor_sync(0xffffffffu, part, off);
            if (lane == 0) attn_p[k][sub] = part;
        }
    }
    __syncthreads();

    // softmax over 25 (one warp), attn==0 -> -inf, NaN -> 0 semantics
    if (t < 32) {
        float v = (lane < NKW) ? (attn_p[lane][0] + attn_p[lane][1]) : -INFINITY;
        if (v == 0.0f) v = -INFINITY;
        float mx = v;
#pragma unroll
        for (int off = 16; off; off >>= 1)
            mx = fmaxf(mx, __shfl_xor_sync(0xffffffffu, mx, off));
        float e = (mx == -INFINITY) ? 0.0f : expf(v - mx);
        float den = e;
#pragma unroll
        for (int off = 16; off; off >>= 1)
            den += __shfl_xor_sync(0xffffffffu, den, off);
        float wv = (den > 0.0f) ? (e / den) : 0.0f;
        if (lane < NKW) w_s[lane] = wv;
    }

    // q-dependent Cext writes (independent of mix)
    __half* crow = g_Cext + (size_t)b * 1024;
    {
        __half qh = __float2half(q);
        __half ql = __float2half(q - __half2float(qh));
        crow[256 + t] = qh;   // qHi
        crow[768 + t] = ql;   // qLo
    }
    __syncthreads();

    // pass 2: re-gather (L2/L1 hits) + weighted mix partials per k-group
    {
        float4 m4 = make_float4(0.0f, 0.0f, 0.0f, 0.0f);
#pragma unroll
        for (int base = 0; base < 28; base += 4) {
            const int k = base + kq;
            if (k < NKW) {
                int xi = min(max(gx + k / 5 - SWIN, 0), GXD - 1);
                int yi = min(max(gy + k % 5 - SWIN, 0), GYD - 1);
                float4 v = *(const float4*)(memory + ((size_t)xi * GYD + yi) * HD + cq);
                const float w = w_s[k];
                m4.x = fmaf(w, v.x, m4.x);
                m4.y = fmaf(w, v.y, m4.y);
                m4.z = fmaf(w, v.z, m4.z);
                m4.w = fmaf(w, v.w, m4.w);
            }
        }
        *(float4*)(&mixp[kq][cq]) = m4;
    }
    __syncthreads();

    // combine 4 k-group partials (64 threads) and write mix split
    if (t < 64) {
        const int c0 = t * 4;
        float4 a0 = *(const float4*)(&mixp[0][c0]);
        float4 a1 = *(const float4*)(&mixp[1][c0]);
        float4 a2 = *(const float4*)(&mixp[2][c0]);
        float4 a3 = *(const float4*)(&mixp[3][c0]);
        float mv[4] = { a0.x + a1.x + a2.x + a3.x,
                        a0.y + a1.y + a2.y + a3.y,
                        a0.z + a1.z + a2.z + a3.z,
                        a0.w + a1.w + a2.w + a3.w };
        __half mh[4], ml[4];
#pragma unroll
        for (int e = 0; e < 4; e++) {
            mh[e] = __float2half(mv[e]);
            ml[e] = __float2half(mv[e] - __half2float(mh[e]));
        }
        __half2 h01; h01.x = mh[0]; h01.y = mh[1];
        __half2 h23; h23.x = mh[2]; h23.y = mh[3];
        __half2 l01; l01.x = ml[0]; l01.y = ml[1];
        __half2 l23; l23.x = ml[2]; l23.y = ml[3];
        *(__half2*)(crow + c0)           = h01;   // mixHi
        *(__half2*)(crow + c0 + 2)       = h23;
        *(__half2*)(crow + 512 + c0)     = l01;   // mixLo
        *(__half2*)(crow + 512 + c0 + 2) = l23;
    }
}

// ---------------- kernel: output GEMM + fused GRU epilogue ----------------------
__global__ __launch_bounds__(128) void tgemm2_kernel(const float* __restrict__ b_out,
                                                     const float* __restrict__ hidden,
                                                     float* __restrict__ out) {
    extern __shared__ char smem[];

    float acc[4][8][4];
#pragma unroll
    for (int mt = 0; mt < 4; mt++)
#pragma unroll
        for (int nt = 0; nt < 8; nt++)
#pragma unroll
            for (int e = 0; e < 4; e++) acc[mt][nt][e] = 0.0f;

    // GEMM over hi columns only (K=512); Cext row stride = 1024
    mma_gemm_main<512>(g_Cext, 1024, g_Wout, 512, smem, acc);

    const int wid = threadIdx.x >> 5, lane = threadIdx.x & 31;
    const int wm = (wid & 1) * 64, wn = (wid >> 1) * 64;
    const int gid = lane >> 2, tig = lane & 3;
#pragma unroll
    for (int mt = 0; mt < 4; mt++) {
        const int rbase = blockIdx.y * 128 + wm + mt * 16 + gid;
#pragma unroll
        for (int nt = 0; nt < 8; nt++) {
            const int c = blockIdx.x * 128 + wn + nt * 8 + 2 * tig;
            float2 bv = *(const float2*)(b_out + c);
#pragma unroll
            for (int half = 0; half < 2; half++) {
                const int r = rbase + half * 8;
                const __half* crow = g_Cext + (size_t)r * 1024;
                __half2 qh2 = *(const __half2*)(crow + 256 + c);
                __half2 ql2 = *(const __half2*)(crow + 768 + c);
                float2 sg2 = *(const float2*)(g_sg + (size_t)r * 256 + c);
                float2 ug2 = *(const float2*)(g_ug + (size_t)r * 256 + c);
                float2 h2  = *(const float2*)(hidden + (size_t)r * 256 + c);
                float q0 = __half2float(qh2.x) + __half2float(ql2.x);
                float q1 = __half2float(qh2.y) + __half2float(ql2.y);
                float v0 = acc[mt][nt][half * 2 + 0] + bv.x;
                float v1 = acc[mt][nt][half * 2 + 1] + bv.y;
                float a0 = tanhf(v0), a1 = tanhf(v1);
                float cu0 = q0 + sg2.x * a0;
                float cu1 = q1 + sg2.y * a1;
                float2 o;
                o.x = cu0 + ug2.x * (h2.x - cu0);
                o.y = cu1 + ug2.y * (h2.y - cu1);
                *(float2*)(out + (size_t)r * 256 + c) = o;
            }
        }
    }
}

// ---------------- launch ---------------------------------------------------------
extern "C" void kernel_launch(void* const* d_in, const int* in_sizes, int n_in,
                              void* d_out, int out_size) {
    const float* input_tensor = (const float*)d_in[0];  // (B, 258)
    const float* hidden       = (const float*)d_in[1];  // (B, 256)
    const float* w_ih         = (const float*)d_in[2];  // (1024, 256)
    const float* b_ih         = (const float*)d_in[3];  // (1024)
    const float* w_hh         = (const float*)d_in[4];  // (1024, 256)
    const float* b_hh         = (const float*)d_in[5];  // (1024)
    const float* w_out        = (const float*)d_in[6];  // (256, 512)
    const float* b_out        = (const float*)d_in[7];  // (256)
    const float* memory       = (const float*)d_in[8];  // (70, 70, 256)
    float* out = (float*)d_out;                         // (B, 256)

    // Host-side, idempotent, not a stream op (capture-safe).
    cudaFuncSetAttribute(tgemm1_kernel, cudaFuncAttributeMaxDynamicSharedMemorySize, SMEM_BYTES);
    cudaFuncSetAttribute(tgemm2_kernel, cudaFuncAttributeMaxDynamicSharedMemorySize, SMEM_BYTES);

    conv_ah_kernel<<<dim3(8192, 1, 2), 256>>>(input_tensor, hidden);
    conv_w_kernel<<<dim3(512, 1, 3), 256>>>(w_ih, w_hh, w_out);
    tgemm1_kernel<<<dim3(8, 128, 2), 128, SMEM_BYTES>>>(b_ih, b_hh);
    phaseB_kernel<<<BSZ, 256>>>(input_tensor, memory);
    tgemm2_kernel<<<dim3(2, 128), 128, SMEM_BYTES>>>(b_out, hidden, out);
}